// round 5
// baseline (speedup 1.0000x reference)
#include <cuda_runtime.h>

// SparseBPNeuralNetwork — fused sparse BP decoder, round 3.
// Change vs round 2: check-node update fused with tanh via the P/Q ratio:
//   tanh(v/2) = (e^v-1)/(e^v+1);  m = P/Q;  2*atanh(m) = log((Q+P)/(Q-P))
// -> 3 MUFU per edge per iter (EX2, RCP, LG2) instead of 4.

#define NV 648
#define NE 1944
#define BATCH 2048
#define NCHK 324
#define TOT (BATCH * NV)

// clamp of m to +-0.999999 mapped to the ratio r = (1+m)/(1-m)
#define RLO 5.0000025e-7f
#define RHI 1.999999e6f
#define VCLAMP 17.0f          // keeps Q = prod(e^v+1) < FLT_MAX

// ---- preprocessed graph/weight data ----
__device__ int    g_var_of[NE];     // edge -> variable
__device__ int    g_eov[NV * 3];    // var,layer -> edge  (slot = layer = e/NV)
__device__ int    g_j1[NE];         // extrinsic same-var partner 1
__device__ int    g_j2[NE];         // extrinsic same-var partner 2
__device__ float2 g_w[4][NE];       // per VN layer: (W[e][j1], W[e][j2])
__device__ float  g_w9[NV][3];      // output weights per var (3 edges)

// ---------------- preprocessing ----------------
__global__ void prep1(const float4* __restrict__ M_out4) {
    int idx = blockIdx.x * blockDim.x + threadIdx.x;     // over NV*NE/4
    if (idx >= NV * NE / 4) return;
    float4 val = M_out4[idx];
    if (val.x == 0.0f && val.y == 0.0f && val.z == 0.0f && val.w == 0.0f) return;
    int lin = idx * 4;
    int v = lin / NE;
    int e = lin - v * NE;
    float vv[4] = {val.x, val.y, val.z, val.w};
#pragma unroll
    for (int k = 0; k < 4; k++) {
        if (vv[k] != 0.0f) {
            int ek = e + k;
            g_var_of[ek] = v;
            g_eov[v * 3 + ek / NV] = ek;
        }
    }
}

__global__ void prep2(const float* __restrict__ W1, const float* __restrict__ W3,
                      const float* __restrict__ W5, const float* __restrict__ W7,
                      const float* __restrict__ W9) {
    int e = blockIdx.x * blockDim.x + threadIdx.x;
    if (e < NE) {
        int v = g_var_of[e];
        int l = e / NV;
        int j1 = g_eov[v * 3 + ((l + 1) % 3)];
        int j2 = g_eov[v * 3 + ((l + 2) % 3)];
        g_j1[e] = j1;
        g_j2[e] = j2;
        g_w[0][e] = make_float2(W1[(size_t)e * NE + j1], W1[(size_t)e * NE + j2]);
        g_w[1][e] = make_float2(W3[(size_t)e * NE + j1], W3[(size_t)e * NE + j2]);
        g_w[2][e] = make_float2(W5[(size_t)e * NE + j1], W5[(size_t)e * NE + j2]);
        g_w[3][e] = make_float2(W7[(size_t)e * NE + j1], W7[(size_t)e * NE + j2]);
    }
    if (e < NV) {
        int v = e;
        g_w9[v][0] = W9[(size_t)v * NE + g_eov[v * 3 + 0]];
        g_w9[v][1] = W9[(size_t)v * NE + g_eov[v * 3 + 1]];
        g_w9[v][2] = W9[(size_t)v * NE + g_eov[v * 3 + 2]];
    }
}

// ---------------- fast math ----------------
__device__ __forceinline__ float sigmoidf(float s) {
    return __fdividef(1.0f, 1.0f + __expf(-s));
}

// fused tanh + extrinsic-product + 2*atanh for one 6-edge check.
// v[k] are the pre-tanh messages; tv[k] = 2*atanh(clamp(prod_{j!=k} tanh(v_j/2)))
__device__ __forceinline__ void cn_fused(const float v[6], float tv[6]) {
    float n[6], d[6];
#pragma unroll
    for (int k = 0; k < 6; k++) {
        float e = __expf(fminf(v[k], VCLAMP));
        n[k] = e - 1.0f;
        d[k] = e + 1.0f;
    }
    // prefix/suffix products for numerator and denominator
    float a1 = n[0] * n[1], a2 = a1 * n[2], a3 = a2 * n[3], a4 = a3 * n[4];
    float b4 = n[5] * n[4], b3 = b4 * n[3], b2 = b3 * n[2], b1 = b2 * n[1];
    float c1 = d[0] * d[1], c2 = c1 * d[2], c3 = c2 * d[3], c4 = c3 * d[4];
    float f4 = d[5] * d[4], f3 = f4 * d[3], f2 = f3 * d[2], f1 = f2 * d[1];
    float P[6], Q[6];
    P[0] = b1;        P[1] = n[0] * b2; P[2] = a1 * b3;
    P[3] = a2 * b4;   P[4] = a3 * n[5]; P[5] = a4;
    Q[0] = f1;        Q[1] = d[0] * f2; Q[2] = c1 * f3;
    Q[3] = c2 * f4;   Q[4] = c3 * d[5]; Q[5] = c4;
#pragma unroll
    for (int k = 0; k < 6; k++) {
        float num = fmaxf(Q[k] + P[k], 1e-33f);   // math: Q>|P|, guard rounding
        float den = fmaxf(Q[k] - P[k], 1e-33f);
        float r = __fdividef(num, den);
        r = fminf(fmaxf(r, RLO), RHI);            // == clamp of m to +-0.999999
        tv[k] = __logf(r);
    }
}

__global__ __launch_bounds__(NCHK)
void bp_main(const float* __restrict__ x, float* __restrict__ out) {
    __shared__ float s_llr[NV];
    __shared__ float s_t[2][NE];

    const int b   = blockIdx.x;
    const int tid = threadIdx.x;           // one check per thread, 324 threads

    s_llr[tid]        = x[b * NV + tid];
    s_llr[tid + NCHK] = x[b * NV + tid + NCHK];

    const int ebase = tid * 6;
    int vo[6], j1[6], j2[6];
#pragma unroll
    for (int k = 0; k < 6; k++) {
        vo[k] = g_var_of[ebase + k];
        j1[k] = g_j1[ebase + k];
        j2[k] = g_j2[ebase + k];
    }
    const int v0 = tid, v1 = tid + NCHK;
    const int e0a = g_eov[v0 * 3 + 0], e0b = g_eov[v0 * 3 + 1], e0c = g_eov[v0 * 3 + 2];
    const int e1a = g_eov[v1 * 3 + 0], e1b = g_eov[v1 * 3 + 1], e1c = g_eov[v1 * 3 + 2];

    __syncthreads();

    float vin[6], tv[6];

    // ---- iteration 1: CN update directly from channel LLRs ----
#pragma unroll
    for (int k = 0; k < 6; k++) vin[k] = s_llr[vo[k]];
    cn_fused(vin, tv);
#pragma unroll
    for (int k = 0; k < 6; k++) s_t[0][ebase + k] = tv[k];
    __syncthreads();

    // out1 (offset 4*TOT)
    {
        float sA = s_t[0][e0a] + s_t[0][e0b] + s_t[0][e0c] + s_llr[v0];
        float sB = s_t[0][e1a] + s_t[0][e1b] + s_t[0][e1c] + s_llr[v1];
        out[4 * TOT + b * NV + v0] = sigmoidf(sA);
        out[4 * TOT + b * NV + v1] = sigmoidf(sB);
    }

    // ---- iterations 2..5: VN update then fused CN ----
    int src = 0;
#pragma unroll
    for (int li = 0; li < 4; li++) {
        const int dst = src ^ 1;
#pragma unroll
        for (int k = 0; k < 6; k++) {
            float2 w = g_w[li][ebase + k];
            vin[k] = w.x * s_t[src][j1[k]] + w.y * s_t[src][j2[k]] + s_llr[vo[k]];
        }
        cn_fused(vin, tv);
        // dst buffer was last read two barriers ago -> safe without extra barrier
#pragma unroll
        for (int k = 0; k < 6; k++) s_t[dst][ebase + k] = tv[k];
        __syncthreads();

        if (li < 3) {
            float sA = s_t[dst][e0a] + s_t[dst][e0b] + s_t[dst][e0c] + s_llr[v0];
            float sB = s_t[dst][e1a] + s_t[dst][e1b] + s_t[dst][e1c] + s_llr[v1];
            int off = (3 - li) * TOT + b * NV;
            out[off + v0] = sigmoidf(sA);
            out[off + v1] = sigmoidf(sB);
        } else {
            float sA = g_w9[v0][0] * s_t[dst][e0a] + g_w9[v0][1] * s_t[dst][e0b]
                     + g_w9[v0][2] * s_t[dst][e0c] + s_llr[v0];
            float sB = g_w9[v1][0] * s_t[dst][e1a] + g_w9[v1][1] * s_t[dst][e1b]
                     + g_w9[v1][2] * s_t[dst][e1c] + s_llr[v1];
            out[b * NV + v0] = sigmoidf(sA);
            out[b * NV + v1] = sigmoidf(sB);
        }
        src = dst;
    }
}

// ---------------- launch ----------------
extern "C" void kernel_launch(void* const* d_in, const int* in_sizes, int n_in,
                              void* d_out, int out_size) {
    // metadata order: x, M_first, M_cn, M_out, bias_matrix, W1, W3, W5, W7, W9, B0..B4
    const float* x     = (const float*)d_in[0];
    const float* M_out = (const float*)d_in[3];
    const float* W1    = (const float*)d_in[5];
    const float* W3    = (const float*)d_in[6];
    const float* W5    = (const float*)d_in[7];
    const float* W7    = (const float*)d_in[8];
    const float* W9    = (const float*)d_in[9];

    const int scan4 = NV * NE / 4;
    prep1<<<(scan4 + 255) / 256, 256>>>((const float4*)M_out);
    prep2<<<(NE + 255) / 256, 256>>>(W1, W3, W5, W7, W9);
    bp_main<<<BATCH, NCHK>>>(x, (float*)d_out);
}

// round 7
// speedup vs baseline: 1.1641x; 1.1641x over previous
#include <cuda_runtime.h>

// SparseBPNeuralNetwork — fused sparse BP decoder, round 6.
// Changes vs round 3/5:
//  * llr values register-cached (removes 6 random LDS per iteration).
//  * packed partner indices (j1|j2<<16) -> fewer registers.
//  * message stores vectorized to STS.64.
//  * __launch_bounds__(324,3) to hold >=3 blocks/SM.
//  * prep2 parallelized over (layer, edge).

#define NV 648
#define NE 1944
#define BATCH 2048
#define NCHK 324
#define TOT (BATCH * NV)

// clamp of m to +-0.999999 mapped to the ratio r = (1+m)/(1-m)
#define RLO 5.0000025e-7f
#define RHI 1.999999e6f
#define VCLAMP 17.0f          // keeps Q = prod(e^v+1) < FLT_MAX

// ---- preprocessed graph/weight data ----
__device__ int    g_var_of[NE];     // edge -> variable
__device__ int    g_eov[NV * 3];    // var,layer -> edge  (slot = layer = e/NV)
__device__ int    g_jp[NE];         // packed partners: j1 | (j2<<16)
__device__ float2 g_w[4][NE];       // per VN layer: (W[e][j1], W[e][j2])
__device__ float  g_w9[NV][3];      // output weights per var (3 edges)

// ---------------- preprocessing ----------------
__global__ void prep1(const float4* __restrict__ M_out4) {
    int idx = blockIdx.x * blockDim.x + threadIdx.x;     // over NV*NE/4
    if (idx >= NV * NE / 4) return;
    float4 val = M_out4[idx];
    if (val.x == 0.0f && val.y == 0.0f && val.z == 0.0f && val.w == 0.0f) return;
    int lin = idx * 4;
    int v = lin / NE;
    int e = lin - v * NE;
    float vv[4] = {val.x, val.y, val.z, val.w};
#pragma unroll
    for (int k = 0; k < 4; k++) {
        if (vv[k] != 0.0f) {
            int ek = e + k;
            g_var_of[ek] = v;
            g_eov[v * 3 + ek / NV] = ek;
        }
    }
}

__global__ void prep2(const float* __restrict__ W1, const float* __restrict__ W3,
                      const float* __restrict__ W5, const float* __restrict__ W7,
                      const float* __restrict__ W9) {
    int idx = blockIdx.x * blockDim.x + threadIdx.x;     // over 4*NE
    if (idx < 4 * NE) {
        int li = idx / NE;
        int e  = idx - li * NE;
        int v  = g_var_of[e];
        int l  = e / NV;
        int j1 = g_eov[v * 3 + ((l + 1) % 3)];
        int j2 = g_eov[v * 3 + ((l + 2) % 3)];
        const float* W = (li == 0) ? W1 : (li == 1) ? W3 : (li == 2) ? W5 : W7;
        g_w[li][e] = make_float2(W[(size_t)e * NE + j1], W[(size_t)e * NE + j2]);
        if (li == 0) g_jp[e] = j1 | (j2 << 16);
    }
    if (idx < NV) {
        int v = idx;
        g_w9[v][0] = W9[(size_t)v * NE + g_eov[v * 3 + 0]];
        g_w9[v][1] = W9[(size_t)v * NE + g_eov[v * 3 + 1]];
        g_w9[v][2] = W9[(size_t)v * NE + g_eov[v * 3 + 2]];
    }
}

// ---------------- fast math ----------------
__device__ __forceinline__ float sigmoidf(float s) {
    return __fdividef(1.0f, 1.0f + __expf(-s));
}

// fused tanh + extrinsic-product + 2*atanh for one 6-edge check.
// v[k] pre-tanh messages; tv[k] = 2*atanh(clamp(prod_{j!=k} tanh(v_j/2)))
__device__ __forceinline__ void cn_fused(const float v[6], float tv[6]) {
    float n[6], d[6];
#pragma unroll
    for (int k = 0; k < 6; k++) {
        float e = __expf(fminf(v[k], VCLAMP));
        n[k] = e - 1.0f;
        d[k] = e + 1.0f;
    }
    float a1 = n[0] * n[1], a2 = a1 * n[2], a3 = a2 * n[3], a4 = a3 * n[4];
    float b4 = n[5] * n[4], b3 = b4 * n[3], b2 = b3 * n[2], b1 = b2 * n[1];
    float c1 = d[0] * d[1], c2 = c1 * d[2], c3 = c2 * d[3], c4 = c3 * d[4];
    float f4 = d[5] * d[4], f3 = f4 * d[3], f2 = f3 * d[2], f1 = f2 * d[1];
    float P[6], Q[6];
    P[0] = b1;        P[1] = n[0] * b2; P[2] = a1 * b3;
    P[3] = a2 * b4;   P[4] = a3 * n[5]; P[5] = a4;
    Q[0] = f1;        Q[1] = d[0] * f2; Q[2] = c1 * f3;
    Q[3] = c2 * f4;   Q[4] = c3 * d[5]; Q[5] = c4;
#pragma unroll
    for (int k = 0; k < 6; k++) {
        float num = fmaxf(Q[k] + P[k], 1e-33f);   // math: Q>|P|, guard rounding
        float den = fmaxf(Q[k] - P[k], 1e-33f);
        float r = __fdividef(num, den);
        r = fminf(fmaxf(r, RLO), RHI);            // == clamp of m to +-0.999999
        tv[k] = __logf(r);
    }
}

__global__ __launch_bounds__(NCHK, 3)
void bp_main(const float* __restrict__ x, float* __restrict__ out) {
    __shared__ float s_llr[NV];
    __shared__ float s_t[2][NE];

    const int b   = blockIdx.x;
    const int tid = threadIdx.x;           // one check per thread, 324 threads

    // coalesced float2 row load: 324 threads x 2 floats = 648
    ((float2*)s_llr)[tid] = ((const float2*)(x + (size_t)b * NV))[tid];

    const int ebase = tid * 6;
    int jp[6], vo[6];
#pragma unroll
    for (int k = 0; k < 6; k++) {
        jp[k] = g_jp[ebase + k];
        vo[k] = g_var_of[ebase + k];
    }
    const int v0 = tid, v1 = tid + NCHK;
    const int e0a = g_eov[v0 * 3 + 0], e0b = g_eov[v0 * 3 + 1], e0c = g_eov[v0 * 3 + 2];
    const int e1a = g_eov[v1 * 3 + 0], e1b = g_eov[v1 * 3 + 1], e1c = g_eov[v1 * 3 + 2];

    __syncthreads();

    // llr values for this thread's 6 edges are fixed across iterations
    float llr_e[6];
#pragma unroll
    for (int k = 0; k < 6; k++) llr_e[k] = s_llr[vo[k]];

    float vin[6], tv[6];

    // ---- iteration 1: CN update directly from channel LLRs ----
#pragma unroll
    for (int k = 0; k < 6; k++) vin[k] = llr_e[k];
    cn_fused(vin, tv);
    {
        float2* st2 = (float2*)&s_t[0][ebase];
        st2[0] = make_float2(tv[0], tv[1]);
        st2[1] = make_float2(tv[2], tv[3]);
        st2[2] = make_float2(tv[4], tv[5]);
    }
    __syncthreads();

    // out1 (offset 4*TOT)
    {
        float sA = s_t[0][e0a] + s_t[0][e0b] + s_t[0][e0c] + s_llr[v0];
        float sB = s_t[0][e1a] + s_t[0][e1b] + s_t[0][e1c] + s_llr[v1];
        out[4 * TOT + (size_t)b * NV + v0] = sigmoidf(sA);
        out[4 * TOT + (size_t)b * NV + v1] = sigmoidf(sB);
    }

    // ---- iterations 2..5: VN update then fused CN ----
    int src = 0;
#pragma unroll
    for (int li = 0; li < 4; li++) {
        const int dst = src ^ 1;
#pragma unroll
        for (int k = 0; k < 6; k++) {
            int j1 = jp[k] & 0xFFFF;
            int j2 = jp[k] >> 16;
            float2 w = g_w[li][ebase + k];
            vin[k] = fmaf(w.x, s_t[src][j1], fmaf(w.y, s_t[src][j2], llr_e[k]));
        }
        cn_fused(vin, tv);
        // dst buffer was last read two barriers ago -> safe without extra barrier
        {
            float2* st2 = (float2*)&s_t[dst][ebase];
            st2[0] = make_float2(tv[0], tv[1]);
            st2[1] = make_float2(tv[2], tv[3]);
            st2[2] = make_float2(tv[4], tv[5]);
        }
        __syncthreads();

        if (li < 3) {
            float sA = s_t[dst][e0a] + s_t[dst][e0b] + s_t[dst][e0c] + s_llr[v0];
            float sB = s_t[dst][e1a] + s_t[dst][e1b] + s_t[dst][e1c] + s_llr[v1];
            size_t off = (size_t)(3 - li) * TOT + (size_t)b * NV;
            out[off + v0] = sigmoidf(sA);
            out[off + v1] = sigmoidf(sB);
        } else {
            float sA = g_w9[v0][0] * s_t[dst][e0a] + g_w9[v0][1] * s_t[dst][e0b]
                     + g_w9[v0][2] * s_t[dst][e0c] + s_llr[v0];
            float sB = g_w9[v1][0] * s_t[dst][e1a] + g_w9[v1][1] * s_t[dst][e1b]
                     + g_w9[v1][2] * s_t[dst][e1c] + s_llr[v1];
            out[(size_t)b * NV + v0] = sigmoidf(sA);
            out[(size_t)b * NV + v1] = sigmoidf(sB);
        }
        src = dst;
    }
}

// ---------------- launch ----------------
extern "C" void kernel_launch(void* const* d_in, const int* in_sizes, int n_in,
                              void* d_out, int out_size) {
    // metadata order: x, M_first, M_cn, M_out, bias_matrix, W1, W3, W5, W7, W9, B0..B4
    const float* x     = (const float*)d_in[0];
    const float* M_out = (const float*)d_in[3];
    const float* W1    = (const float*)d_in[5];
    const float* W3    = (const float*)d_in[6];
    const float* W5    = (const float*)d_in[7];
    const float* W7    = (const float*)d_in[8];
    const float* W9    = (const float*)d_in[9];

    const int scan4 = NV * NE / 4;
    prep1<<<(scan4 + 255) / 256, 256>>>((const float4*)M_out);
    prep2<<<(4 * NE + 255) / 256, 256>>>(W1, W3, W5, W7, W9);
    bp_main<<<BATCH, NCHK>>>(x, (float*)d_out);
}

// round 8
// speedup vs baseline: 1.1899x; 1.0222x over previous
#include <cuda_runtime.h>

// SparseBPNeuralNetwork — fused sparse BP decoder, round 8.
// Changes vs round 6:
//  * bp_main: ROWS=2 batch rows per block -> 2 independent ILP chains per
//    thread, halved barrier count per row, same LDS/MUFU totals.
//  * prep1: 4 strided float4 loads per thread (MLP=4, latency-bound fix).

#define NV 648
#define NE 1944
#define BATCH 2048
#define NCHK 324
#define TOT (BATCH * NV)
#define ROWS 2

// clamp of m to +-0.999999 mapped to the ratio r = (1+m)/(1-m)
#define RLO 5.0000025e-7f
#define RHI 1.999999e6f
#define VCLAMP 17.0f          // keeps Q = prod(e^v+1) < FLT_MAX

// ---- preprocessed graph/weight data ----
__device__ int    g_var_of[NE];     // edge -> variable
__device__ int    g_eov[NV * 3];    // var,layer -> edge  (slot = layer = e/NV)
__device__ int    g_jp[NE];         // packed partners: j1 | (j2<<16)
__device__ float2 g_w[4][NE];       // per VN layer: (W[e][j1], W[e][j2])
__device__ float  g_w9[NV][3];      // output weights per var (3 edges)

// ---------------- preprocessing ----------------
#define SCAN4 (NV * NE / 4)
#define P1_THREADS ((SCAN4 + 3) / 4)

__global__ void prep1(const float4* __restrict__ M_out4) {
    int t = blockIdx.x * blockDim.x + threadIdx.x;
    // 4 strided loads per thread -> MLP=4, all coalesced
    float4 val[4];
    int idx[4];
#pragma unroll
    for (int s = 0; s < 4; s++) {
        idx[s] = t + s * P1_THREADS;
        if (idx[s] < SCAN4) val[s] = M_out4[idx[s]];
        else                val[s] = make_float4(0.f, 0.f, 0.f, 0.f);
    }
#pragma unroll
    for (int s = 0; s < 4; s++) {
        float vv[4] = {val[s].x, val[s].y, val[s].z, val[s].w};
        if (vv[0] == 0.f && vv[1] == 0.f && vv[2] == 0.f && vv[3] == 0.f) continue;
        int lin = idx[s] * 4;
        int v = lin / NE;
        int e = lin - v * NE;
#pragma unroll
        for (int k = 0; k < 4; k++) {
            if (vv[k] != 0.0f) {
                int ek = e + k;
                g_var_of[ek] = v;
                g_eov[v * 3 + ek / NV] = ek;
            }
        }
    }
}

__global__ void prep2(const float* __restrict__ W1, const float* __restrict__ W3,
                      const float* __restrict__ W5, const float* __restrict__ W7,
                      const float* __restrict__ W9) {
    int idx = blockIdx.x * blockDim.x + threadIdx.x;     // over 4*NE
    if (idx < 4 * NE) {
        int li = idx / NE;
        int e  = idx - li * NE;
        int v  = g_var_of[e];
        int l  = e / NV;
        int j1 = g_eov[v * 3 + ((l + 1) % 3)];
        int j2 = g_eov[v * 3 + ((l + 2) % 3)];
        const float* W = (li == 0) ? W1 : (li == 1) ? W3 : (li == 2) ? W5 : W7;
        g_w[li][e] = make_float2(W[(size_t)e * NE + j1], W[(size_t)e * NE + j2]);
        if (li == 0) g_jp[e] = j1 | (j2 << 16);
    }
    if (idx < NV) {
        int v = idx;
        g_w9[v][0] = W9[(size_t)v * NE + g_eov[v * 3 + 0]];
        g_w9[v][1] = W9[(size_t)v * NE + g_eov[v * 3 + 1]];
        g_w9[v][2] = W9[(size_t)v * NE + g_eov[v * 3 + 2]];
    }
}

// ---------------- fast math ----------------
__device__ __forceinline__ float sigmoidf(float s) {
    return __fdividef(1.0f, 1.0f + __expf(-s));
}

// fused tanh + extrinsic-product + 2*atanh for one 6-edge check.
__device__ __forceinline__ void cn_fused(const float v[6], float tv[6]) {
    float n[6], d[6];
#pragma unroll
    for (int k = 0; k < 6; k++) {
        float e = __expf(fminf(v[k], VCLAMP));
        n[k] = e - 1.0f;
        d[k] = e + 1.0f;
    }
    float a1 = n[0] * n[1], a2 = a1 * n[2], a3 = a2 * n[3], a4 = a3 * n[4];
    float b4 = n[5] * n[4], b3 = b4 * n[3], b2 = b3 * n[2], b1 = b2 * n[1];
    float c1 = d[0] * d[1], c2 = c1 * d[2], c3 = c2 * d[3], c4 = c3 * d[4];
    float f4 = d[5] * d[4], f3 = f4 * d[3], f2 = f3 * d[2], f1 = f2 * d[1];
    float P[6], Q[6];
    P[0] = b1;        P[1] = n[0] * b2; P[2] = a1 * b3;
    P[3] = a2 * b4;   P[4] = a3 * n[5]; P[5] = a4;
    Q[0] = f1;        Q[1] = d[0] * f2; Q[2] = c1 * f3;
    Q[3] = c2 * f4;   Q[4] = c3 * d[5]; Q[5] = c4;
#pragma unroll
    for (int k = 0; k < 6; k++) {
        float num = fmaxf(Q[k] + P[k], 1e-33f);
        float den = fmaxf(Q[k] - P[k], 1e-33f);
        float r = __fdividef(num, den);
        r = fminf(fmaxf(r, RLO), RHI);            // == clamp of m to +-0.999999
        tv[k] = __logf(r);
    }
}

__global__ __launch_bounds__(NCHK, 2)
void bp_main(const float* __restrict__ x, float* __restrict__ out) {
    __shared__ float s_llr[ROWS][NV];
    __shared__ float s_t[ROWS][2][NE];

    const int b0  = blockIdx.x * ROWS;
    const int tid = threadIdx.x;           // one check per thread, 324 threads

#pragma unroll
    for (int r = 0; r < ROWS; r++)
        ((float2*)s_llr[r])[tid] = ((const float2*)(x + (size_t)(b0 + r) * NV))[tid];

    const int ebase = tid * 6;
    int jp[6], vo[6];
#pragma unroll
    for (int k = 0; k < 6; k++) {
        jp[k] = g_jp[ebase + k];
        vo[k] = g_var_of[ebase + k];
    }
    const int v0 = tid, v1 = tid + NCHK;
    const int e0a = g_eov[v0 * 3 + 0], e0b = g_eov[v0 * 3 + 1], e0c = g_eov[v0 * 3 + 2];
    const int e1a = g_eov[v1 * 3 + 0], e1b = g_eov[v1 * 3 + 1], e1c = g_eov[v1 * 3 + 2];

    __syncthreads();

    // llr values for this thread's 6 edges, per row (fixed across iterations)
    float llr_e[ROWS][6];
#pragma unroll
    for (int r = 0; r < ROWS; r++)
#pragma unroll
        for (int k = 0; k < 6; k++) llr_e[r][k] = s_llr[r][vo[k]];

    // ---- iteration 1: CN update directly from channel LLRs ----
#pragma unroll
    for (int r = 0; r < ROWS; r++) {
        float tv[6];
        cn_fused(llr_e[r], tv);
        float2* st2 = (float2*)&s_t[r][0][ebase];
        st2[0] = make_float2(tv[0], tv[1]);
        st2[1] = make_float2(tv[2], tv[3]);
        st2[2] = make_float2(tv[4], tv[5]);
    }
    __syncthreads();

    // out1 (offset 4*TOT)
#pragma unroll
    for (int r = 0; r < ROWS; r++) {
        float sA = s_t[r][0][e0a] + s_t[r][0][e0b] + s_t[r][0][e0c] + s_llr[r][v0];
        float sB = s_t[r][0][e1a] + s_t[r][0][e1b] + s_t[r][0][e1c] + s_llr[r][v1];
        out[4 * (size_t)TOT + (size_t)(b0 + r) * NV + v0] = sigmoidf(sA);
        out[4 * (size_t)TOT + (size_t)(b0 + r) * NV + v1] = sigmoidf(sB);
    }

    // ---- iterations 2..5: VN update then fused CN ----
    int src = 0;
#pragma unroll
    for (int li = 0; li < 4; li++) {
        const int dst = src ^ 1;
#pragma unroll
        for (int r = 0; r < ROWS; r++) {
            float vin[6], tv[6];
#pragma unroll
            for (int k = 0; k < 6; k++) {
                int j1 = jp[k] & 0xFFFF;
                int j2 = jp[k] >> 16;
                float2 w = g_w[li][ebase + k];
                vin[k] = fmaf(w.x, s_t[r][src][j1],
                              fmaf(w.y, s_t[r][src][j2], llr_e[r][k]));
            }
            cn_fused(vin, tv);
            // dst buffer was last read two barriers ago -> safe without extra barrier
            float2* st2 = (float2*)&s_t[r][dst][ebase];
            st2[0] = make_float2(tv[0], tv[1]);
            st2[1] = make_float2(tv[2], tv[3]);
            st2[2] = make_float2(tv[4], tv[5]);
        }
        __syncthreads();

        if (li < 3) {
#pragma unroll
            for (int r = 0; r < ROWS; r++) {
                float sA = s_t[r][dst][e0a] + s_t[r][dst][e0b] + s_t[r][dst][e0c] + s_llr[r][v0];
                float sB = s_t[r][dst][e1a] + s_t[r][dst][e1b] + s_t[r][dst][e1c] + s_llr[r][v1];
                size_t off = (size_t)(3 - li) * TOT + (size_t)(b0 + r) * NV;
                out[off + v0] = sigmoidf(sA);
                out[off + v1] = sigmoidf(sB);
            }
        } else {
            float w9a0 = g_w9[v0][0], w9a1 = g_w9[v0][1], w9a2 = g_w9[v0][2];
            float w9b0 = g_w9[v1][0], w9b1 = g_w9[v1][1], w9b2 = g_w9[v1][2];
#pragma unroll
            for (int r = 0; r < ROWS; r++) {
                float sA = w9a0 * s_t[r][dst][e0a] + w9a1 * s_t[r][dst][e0b]
                         + w9a2 * s_t[r][dst][e0c] + s_llr[r][v0];
                float sB = w9b0 * s_t[r][dst][e1a] + w9b1 * s_t[r][dst][e1b]
                         + w9b2 * s_t[r][dst][e1c] + s_llr[r][v1];
                out[(size_t)(b0 + r) * NV + v0] = sigmoidf(sA);
                out[(size_t)(b0 + r) * NV + v1] = sigmoidf(sB);
            }
        }
        src = dst;
    }
}

// ---------------- launch ----------------
extern "C" void kernel_launch(void* const* d_in, const int* in_sizes, int n_in,
                              void* d_out, int out_size) {
    // metadata order: x, M_first, M_cn, M_out, bias_matrix, W1, W3, W5, W7, W9, B0..B4
    const float* x     = (const float*)d_in[0];
    const float* M_out = (const float*)d_in[3];
    const float* W1    = (const float*)d_in[5];
    const float* W3    = (const float*)d_in[6];
    const float* W5    = (const float*)d_in[7];
    const float* W7    = (const float*)d_in[8];
    const float* W9    = (const float*)d_in[9];

    prep1<<<(P1_THREADS + 255) / 256, 256>>>((const float4*)M_out);
    prep2<<<(4 * NE + 255) / 256, 256>>>(W1, W3, W5, W7, W9);
    bp_main<<<BATCH / ROWS, NCHK>>>(x, (float*)d_out);
}

// round 9
// speedup vs baseline: 1.2224x; 1.0273x over previous
#include <cuda_runtime.h>

// SparseBPNeuralNetwork — fused sparse BP decoder, round 9.
// Changes vs round 8:
//  * messages + llr stored as float2 (row0,row1): every random smem gather
//    is one LDS.64 serving both batch rows; forces row-interleaved MUFU.
//  * 2*atanh via independent log2 pair + clamp on the result (shorter chain).
//  * llr[v0], llr[v1], w9 register-cached.

#define NV 648
#define NE 1944
#define BATCH 2048
#define NCHK 324
#define TOT (BATCH * NV)
#define ROWS 2

#define VCLAMP 17.0f            // keeps Q = prod(e^v+1) < FLT_MAX
#define TVCLAMP 14.508657f      // = 2*atanh(0.999999) = ln(1.999999/1e-6)
#define LN2F 0.69314718056f

// ---- preprocessed graph/weight data ----
__device__ int    g_var_of[NE];     // edge -> variable
__device__ int    g_eov[NV * 3];    // var,layer -> edge  (slot = layer = e/NV)
__device__ int    g_jp[NE];         // packed partners: j1 | (j2<<16)
__device__ float2 g_w[4][NE];       // per VN layer: (W[e][j1], W[e][j2])
__device__ float  g_w9[NV][3];      // output weights per var (3 edges)

// ---------------- preprocessing ----------------
#define SCAN4 (NV * NE / 4)

__global__ void prep1(const float4* __restrict__ M_out4) {
    int idx = blockIdx.x * blockDim.x + threadIdx.x;     // over NV*NE/4
    if (idx >= SCAN4) return;
    float4 val = M_out4[idx];
    if (val.x == 0.0f && val.y == 0.0f && val.z == 0.0f && val.w == 0.0f) return;
    int lin = idx * 4;
    int v = lin / NE;
    int e = lin - v * NE;
    float vv[4] = {val.x, val.y, val.z, val.w};
#pragma unroll
    for (int k = 0; k < 4; k++) {
        if (vv[k] != 0.0f) {
            int ek = e + k;
            g_var_of[ek] = v;
            g_eov[v * 3 + ek / NV] = ek;
        }
    }
}

__global__ void prep2(const float* __restrict__ W1, const float* __restrict__ W3,
                      const float* __restrict__ W5, const float* __restrict__ W7,
                      const float* __restrict__ W9) {
    int idx = blockIdx.x * blockDim.x + threadIdx.x;     // over 4*NE
    if (idx < 4 * NE) {
        int li = idx / NE;
        int e  = idx - li * NE;
        int v  = g_var_of[e];
        int l  = e / NV;
        int j1 = g_eov[v * 3 + ((l + 1) % 3)];
        int j2 = g_eov[v * 3 + ((l + 2) % 3)];
        const float* W = (li == 0) ? W1 : (li == 1) ? W3 : (li == 2) ? W5 : W7;
        g_w[li][e] = make_float2(W[(size_t)e * NE + j1], W[(size_t)e * NE + j2]);
        if (li == 0) g_jp[e] = j1 | (j2 << 16);
    }
    if (idx < NV) {
        int v = idx;
        g_w9[v][0] = W9[(size_t)v * NE + g_eov[v * 3 + 0]];
        g_w9[v][1] = W9[(size_t)v * NE + g_eov[v * 3 + 1]];
        g_w9[v][2] = W9[(size_t)v * NE + g_eov[v * 3 + 2]];
    }
}

// ---------------- fast math ----------------
__device__ __forceinline__ float sigmoidf(float s) {
    return __fdividef(1.0f, 1.0f + __expf(-s));
}

// fused tanh + extrinsic-product + 2*atanh for one 6-edge check, both rows.
// v[k] = pre-tanh messages (x=row0, y=row1);
// tv[k] = 2*atanh(clamp(prod_{j!=k} tanh(v_j/2))) per row.
__device__ __forceinline__ void cn_fused2(const float2 v[6], float2 tv[6]) {
    float2 n[6], d[6];
#pragma unroll
    for (int k = 0; k < 6; k++) {
        float ex = __expf(fminf(v[k].x, VCLAMP));
        float ey = __expf(fminf(v[k].y, VCLAMP));
        n[k] = make_float2(ex - 1.0f, ey - 1.0f);
        d[k] = make_float2(ex + 1.0f, ey + 1.0f);
    }
#define M2(a, b) make_float2((a).x * (b).x, (a).y * (b).y)
    float2 a1 = M2(n[0], n[1]), a2 = M2(a1, n[2]), a3 = M2(a2, n[3]), a4 = M2(a3, n[4]);
    float2 b4 = M2(n[5], n[4]), b3 = M2(b4, n[3]), b2 = M2(b3, n[2]), b1 = M2(b2, n[1]);
    float2 c1 = M2(d[0], d[1]), c2 = M2(c1, d[2]), c3 = M2(c2, d[3]), c4 = M2(c3, d[4]);
    float2 f4 = M2(d[5], d[4]), f3 = M2(f4, d[3]), f2 = M2(f3, d[2]), f1 = M2(f2, d[1]);
    float2 P[6], Q[6];
    P[0] = b1;            P[1] = M2(n[0], b2);  P[2] = M2(a1, b3);
    P[3] = M2(a2, b4);    P[4] = M2(a3, n[5]);  P[5] = a4;
    Q[0] = f1;            Q[1] = M2(d[0], f2);  Q[2] = M2(c1, f3);
    Q[3] = M2(c2, f4);    Q[4] = M2(c3, d[5]);  Q[5] = c4;
#undef M2
#pragma unroll
    for (int k = 0; k < 6; k++) {
        // independent log2 of num and den -> shorter dependency chain than div+log
        float nx = fmaxf(Q[k].x + P[k].x, 1e-33f);
        float dx = fmaxf(Q[k].x - P[k].x, 1e-33f);
        float ny = fmaxf(Q[k].y + P[k].y, 1e-33f);
        float dy = fmaxf(Q[k].y - P[k].y, 1e-33f);
        float tx = (__log2f(nx) - __log2f(dx)) * LN2F;
        float ty = (__log2f(ny) - __log2f(dy)) * LN2F;
        tv[k].x = fminf(fmaxf(tx, -TVCLAMP), TVCLAMP);   // == clamp m to +-0.999999
        tv[k].y = fminf(fmaxf(ty, -TVCLAMP), TVCLAMP);
    }
}

__global__ __launch_bounds__(NCHK, 2)
void bp_main(const float* __restrict__ x, float* __restrict__ out) {
    __shared__ float2 s_llr[NV];        // (row0, row1)
    __shared__ float2 s_t[2][NE];       // messages, row-interleaved

    const int b0  = blockIdx.x * ROWS;
    const int tid = threadIdx.x;        // one check per thread, 324 threads

    // coalesced loads of both rows, interleave into s_llr
    {
        float2 a = ((const float2*)(x + (size_t)b0 * NV))[tid];
        float2 c = ((const float2*)(x + (size_t)(b0 + 1) * NV))[tid];
        s_llr[2 * tid]     = make_float2(a.x, c.x);
        s_llr[2 * tid + 1] = make_float2(a.y, c.y);
    }

    const int ebase = tid * 6;
    int jp[6], vo[6];
#pragma unroll
    for (int k = 0; k < 6; k++) {
        jp[k] = g_jp[ebase + k];
        vo[k] = g_var_of[ebase + k];
    }
    const int v0 = tid, v1 = tid + NCHK;
    const int e0a = g_eov[v0 * 3 + 0], e0b = g_eov[v0 * 3 + 1], e0c = g_eov[v0 * 3 + 2];
    const int e1a = g_eov[v1 * 3 + 0], e1b = g_eov[v1 * 3 + 1], e1c = g_eov[v1 * 3 + 2];

    __syncthreads();

    // register-cache llr for this thread's 6 edges and its 2 output vars
    float2 llr_e[6];
#pragma unroll
    for (int k = 0; k < 6; k++) llr_e[k] = s_llr[vo[k]];
    const float2 llrv0 = s_llr[v0], llrv1 = s_llr[v1];

    float2 tv[6];

    // ---- iteration 1: CN update directly from channel LLRs ----
    cn_fused2(llr_e, tv);
#pragma unroll
    for (int k = 0; k < 6; k++) s_t[0][ebase + k] = tv[k];
    __syncthreads();

    // out1 (offset 4*TOT)
    {
        float2 ta = s_t[0][e0a], tb = s_t[0][e0b], tc = s_t[0][e0c];
        float2 ua = s_t[0][e1a], ub = s_t[0][e1b], uc = s_t[0][e1c];
        size_t off0 = 4 * (size_t)TOT + (size_t)b0 * NV;
        out[off0 + v0]      = sigmoidf(ta.x + tb.x + tc.x + llrv0.x);
        out[off0 + v1]      = sigmoidf(ua.x + ub.x + uc.x + llrv1.x);
        out[off0 + NV + v0] = sigmoidf(ta.y + tb.y + tc.y + llrv0.y);
        out[off0 + NV + v1] = sigmoidf(ua.y + ub.y + uc.y + llrv1.y);
    }

    // ---- iterations 2..5: VN update then fused CN ----
    int src = 0;
#pragma unroll
    for (int li = 0; li < 4; li++) {
        const int dst = src ^ 1;
        float2 vin[6];
#pragma unroll
        for (int k = 0; k < 6; k++) {
            int j1 = jp[k] & 0xFFFF;
            int j2 = jp[k] >> 16;
            float2 t1 = s_t[src][j1];            // one LDS.64 serves both rows
            float2 t2 = s_t[src][j2];
            float2 w  = g_w[li][ebase + k];
            vin[k].x = fmaf(w.x, t1.x, fmaf(w.y, t2.x, llr_e[k].x));
            vin[k].y = fmaf(w.x, t1.y, fmaf(w.y, t2.y, llr_e[k].y));
        }
        cn_fused2(vin, tv);
        // dst buffer was last read two barriers ago -> safe without extra barrier
#pragma unroll
        for (int k = 0; k < 6; k++) s_t[dst][ebase + k] = tv[k];
        __syncthreads();

        float2 ta = s_t[dst][e0a], tb = s_t[dst][e0b], tc = s_t[dst][e0c];
        float2 ua = s_t[dst][e1a], ub = s_t[dst][e1b], uc = s_t[dst][e1c];
        if (li < 3) {
            size_t off0 = (size_t)(3 - li) * TOT + (size_t)b0 * NV;
            out[off0 + v0]      = sigmoidf(ta.x + tb.x + tc.x + llrv0.x);
            out[off0 + v1]      = sigmoidf(ua.x + ub.x + uc.x + llrv1.x);
            out[off0 + NV + v0] = sigmoidf(ta.y + tb.y + tc.y + llrv0.y);
            out[off0 + NV + v1] = sigmoidf(ua.y + ub.y + uc.y + llrv1.y);
        } else {
            float w9a0 = g_w9[v0][0], w9a1 = g_w9[v0][1], w9a2 = g_w9[v0][2];
            float w9b0 = g_w9[v1][0], w9b1 = g_w9[v1][1], w9b2 = g_w9[v1][2];
            size_t off0 = (size_t)b0 * NV;
            out[off0 + v0]      = sigmoidf(w9a0 * ta.x + w9a1 * tb.x + w9a2 * tc.x + llrv0.x);
            out[off0 + v1]      = sigmoidf(w9b0 * ua.x + w9b1 * ub.x + w9b2 * uc.x + llrv1.x);
            out[off0 + NV + v0] = sigmoidf(w9a0 * ta.y + w9a1 * tb.y + w9a2 * tc.y + llrv0.y);
            out[off0 + NV + v1] = sigmoidf(w9b0 * ua.y + w9b1 * ub.y + w9b2 * uc.y + llrv1.y);
        }
        src = dst;
    }
}

// ---------------- launch ----------------
extern "C" void kernel_launch(void* const* d_in, const int* in_sizes, int n_in,
                              void* d_out, int out_size) {
    // metadata order: x, M_first, M_cn, M_out, bias_matrix, W1, W3, W5, W7, W9, B0..B4
    const float* x     = (const float*)d_in[0];
    const float* M_out = (const float*)d_in[3];
    const float* W1    = (const float*)d_in[5];
    const float* W3    = (const float*)d_in[6];
    const float* W5    = (const float*)d_in[7];
    const float* W7    = (const float*)d_in[8];
    const float* W9    = (const float*)d_in[9];

    prep1<<<(SCAN4 + 255) / 256, 256>>>((const float4*)M_out);
    prep2<<<(4 * NE + 255) / 256, 256>>>(W1, W3, W5, W7, W9);
    bp_main<<<BATCH / ROWS, NCHK>>>(x, (float*)d_out);
}